// round 11
// baseline (speedup 1.0000x reference)
#include <cuda_runtime.h>
#include <cuda_bf16.h>

// SemiLoss focal loss (gamma=6), single fused kernel.
// Hybrid of the two fastest measured variants (re-bench of R9; prior round
// failed on infra, not kernel):
//   - 128-thread blocks, 1024-px units (finest block spread, R8)
//   - vectorized consecutive-4 seg loads (int4 / longlong2 pairs, R3)
//   - __expf fast-path, trimmed single-sync prologue
//
//   logits : [N, K, P] f32
//   seg    : [N, P]    int64 or int32 (runtime-sniffed)
//   label  : [N]       same int dtype
//   loss = -sum_{n: label[n]!=0} sum_p (1-exp(lp))^6 * lp / count(label!=0)
//   out  = [loss, 0, loss, 0, ...]
//
// Completion: atomicAdd(g_total) + threadfence + atomicInc(g_done) wrapping
// at gridDim.x (self-resetting); last block finalizes out and resets g_total
// so the kernel is deterministic across CUDA-graph replays.

#define THREADS   128
#define UNIT_PX   1024               // 128 thr * 8 px
#define MAXROWS   128                // N <= 128 (single-pass ballot mapper)

__device__ double       g_total = 0.0;
__device__ unsigned int g_done  = 0u;

__device__ __forceinline__ float focal_term(float lp)
{
    float pt = __expf(lp);
    float u  = 1.0f - pt;
    float u2 = u * u;
    return u2 * u2 * u2 * lp;   // positive form; negated at the end
}

__global__ __launch_bounds__(THREADS)
void semiloss_fused(const float* __restrict__ logits,
                    const void*  __restrict__ seg,
                    const void*  __restrict__ label,
                    int N, int K, int P, int unitsPerRow,
                    float* __restrict__ out, int out_size)
{
    const int tid = threadIdx.x;

    // ---- prologue: dtype sniff + active-row ballot map ----
    __shared__ int      s_is64;
    __shared__ unsigned s_masks[MAXROWS / 32];
    __shared__ short    s_rowOf[MAXROWS];   // ordinal -> row
    const int nwords = (N + 31) >> 5;

    if (tid < 32) {
        // int64 (LE) => every odd 32-bit word of seg is 0
        const int* w = (const int*)seg;
        unsigned b = __ballot_sync(0xffffffffu, w[2 * tid + 1] == 0);
        if (tid == 0) s_is64 = (b == 0xffffffffu) ? 1 : 0;
    }
    __syncthreads();
    const int is64 = s_is64;

    {
        bool a = false;
        if (tid < N) {
            long long lv;
            if (is64) lv = ((const long long*)label)[tid];
            else      lv = (long long)((const int*)label)[tid];
            a = (lv != 0);
        }
        unsigned b = __ballot_sync(0xffffffffu, a);
        if ((tid & 31) == 0 && (tid >> 5) < nwords)
            s_masks[tid >> 5] = b;
    }
    __syncthreads();

    int cnt = 0;
    #pragma unroll 4
    for (int j = 0; j < nwords; ++j) cnt += __popc(s_masks[j]);

    if (tid < N) {
        int w = tid >> 5, l = tid & 31;
        if ((s_masks[w] >> l) & 1u) {
            int pre = __popc(s_masks[w] & ((1u << l) - 1u));
            for (int j = 0; j < w; ++j) pre += __popc(s_masks[j]);
            s_rowOf[pre] = (short)tid;
        }
    }
    __syncthreads();

    // ---- gather-reduce over this block's unit (if any) ----
    float acc = 0.0f;
    {
        const int u = blockIdx.x;
        const int q = u / unitsPerRow;             // active-row ordinal
        if (q < cnt) {
            const int sub = u - q * unitsPerRow;
            const int row = s_rowOf[q];
            const int pA  = sub * UNIT_PX + 4 * tid;      // group A (4 consec px)
            const int pB  = pA + 512;                     // group B
            const float* base = logits + (size_t)row * (size_t)K * (size_t)P;

            if (pB + 4 <= P) {
                int c[8];
                if (is64) {
                    const long long* s = (const long long*)seg + (size_t)row * P;
                    const longlong2* sa = (const longlong2*)(s + pA);
                    const longlong2* sb = (const longlong2*)(s + pB);
                    longlong2 a0 = __ldg(sa), a1 = __ldg(sa + 1);
                    longlong2 b0 = __ldg(sb), b1 = __ldg(sb + 1);
                    c[0] = (int)a0.x; c[1] = (int)a0.y; c[2] = (int)a1.x; c[3] = (int)a1.y;
                    c[4] = (int)b0.x; c[5] = (int)b0.y; c[6] = (int)b1.x; c[7] = (int)b1.y;
                } else {
                    const int* s = (const int*)seg + (size_t)row * P;
                    int4 a = __ldg((const int4*)(s + pA));
                    int4 b = __ldg((const int4*)(s + pB));
                    c[0] = a.x; c[1] = a.y; c[2] = a.z; c[3] = a.w;
                    c[4] = b.x; c[5] = b.y; c[6] = b.z; c[7] = b.w;
                }
                float l[8];
                #pragma unroll
                for (int i = 0; i < 4; ++i)
                    l[i] = __ldg(base + (size_t)c[i] * P + pA + i);
                #pragma unroll
                for (int i = 0; i < 4; ++i)
                    l[4 + i] = __ldg(base + (size_t)c[4 + i] * P + pB + i);
                #pragma unroll
                for (int i = 0; i < 8; ++i)
                    acc += focal_term(l[i]);
            } else {
                // tail unit: scalar fallback over the unit's valid pixels
                int pEnd = sub * UNIT_PX + UNIT_PX;
                if (pEnd > P) pEnd = P;
                for (int p = sub * UNIT_PX + tid; p < pEnd; p += THREADS) {
                    int cc;
                    if (is64) cc = (int)((const long long*)seg)[(size_t)row * P + p];
                    else      cc = ((const int*)seg)[(size_t)row * P + p];
                    acc += focal_term(__ldg(base + (size_t)cc * P + p));
                }
            }
        }
    }

    // ---- block reduction (4 warps) ----
    for (int off = 16; off > 0; off >>= 1)
        acc += __shfl_down_sync(0xffffffffu, acc, off);
    __shared__ double s_part[4];
    const int lane = tid & 31, wid = tid >> 5;
    if (lane == 0) s_part[wid] = (double)acc;
    __syncthreads();

    __shared__ int s_islast;
    if (tid == 0) {
        double v = s_part[0] + s_part[1] + s_part[2] + s_part[3];
        if (v != 0.0) atomicAdd(&g_total, v);
        __threadfence();
        unsigned old = atomicInc(&g_done, gridDim.x - 1u);
        s_islast = (old == gridDim.x - 1u) ? 1 : 0;
    }
    __syncthreads();

    // ---- last block: finalize ----
    if (s_islast) {
        __shared__ float s_loss;
        if (tid == 0) {
            double tot = *((volatile double*)&g_total);
            double cd  = (cnt > 0) ? (double)cnt : 1.0;
            s_loss = (float)(-tot / cd);
            g_total = 0.0;          // reset for next graph replay
            __threadfence();
        }
        __syncthreads();
        float loss = s_loss;
        for (int i = tid; i < out_size; i += blockDim.x)
            out[i] = (i == 0 || i == 2) ? loss : 0.0f;
    }
}

extern "C" void kernel_launch(void* const* d_in, const int* in_sizes, int n_in,
                              void* d_out, int out_size)
{
    const float* logits = (const float*)d_in[0];
    const void*  seg    = d_in[1];
    const void*  label  = d_in[2];

    int N = in_sizes[2];                 // B*S
    int P = in_sizes[1] / N;             // H*W
    int K = in_sizes[0] / in_sizes[1];   // classes

    int unitsPerRow = (P + UNIT_PX - 1) / UNIT_PX;
    unsigned int blocks = (unsigned int)N * (unsigned int)unitsPerRow;

    semiloss_fused<<<blocks, THREADS>>>(logits, seg, label,
                                        N, K, P, unitsPerRow,
                                        (float*)d_out, out_size);
}

// round 12
// speedup vs baseline: 1.0963x; 1.0963x over previous
#include <cuda_runtime.h>
#include <cuda_bf16.h>

// SemiLoss focal loss (gamma=6), single fused kernel.
// Exactly the measured-best memory pattern (R3): 256-thread blocks, 2048-px
// chunks, scalar stride-256 seg loads, 8 px/thread, 32-consecutive-px warp
// gathers. Only changes vs R3: O(1) ballot prologue (replaces the serial
// tid-0 row scan) and __expf.
//
//   logits : [N, K, P] f32
//   seg    : [N, P]    int64 or int32 (runtime-sniffed)
//   label  : [N]       same int dtype
//   loss = -sum_{n: label[n]!=0} sum_p (1-exp(lp))^6 * lp / count(label!=0)
//   out  = [loss, 0, loss, 0, ...]
//
// Completion: atomicAdd(g_total) + threadfence + atomicInc(g_done) wrapping
// at gridDim.x (self-resetting); last block finalizes out and resets g_total
// so the kernel is deterministic across CUDA-graph replays.

#define THREADS   256
#define PXPT      8                    // pixels per thread
#define CHUNK_PX  (THREADS * PXPT)     // 2048
#define MAXROWS   256                  // N <= 256 (ballot mapper)

__device__ double       g_total = 0.0;
__device__ unsigned int g_done  = 0u;

__device__ __forceinline__ float focal_term(float lp)
{
    float pt = __expf(lp);
    float u  = 1.0f - pt;
    float u2 = u * u;
    return u2 * u2 * u2 * lp;   // positive form; negated at the end
}

__global__ __launch_bounds__(THREADS)
void semiloss_fused(const float* __restrict__ logits,
                    const void*  __restrict__ seg,
                    const void*  __restrict__ label,
                    int N, int K, int P, int chunksPerRow,
                    float* __restrict__ out, int out_size)
{
    const int tid = threadIdx.x;

    // ---- prologue: dtype sniff + active-row ballot map ----
    __shared__ int      s_is64;
    __shared__ unsigned s_masks[MAXROWS / 32];
    __shared__ short    s_rowOf[MAXROWS];   // ordinal -> row
    const int nwords = (N + 31) >> 5;

    if (tid < 32) {
        // int64 (LE) => every odd 32-bit word of seg is 0
        const int* w = (const int*)seg;
        unsigned b = __ballot_sync(0xffffffffu, w[2 * tid + 1] == 0);
        if (tid == 0) s_is64 = (b == 0xffffffffu) ? 1 : 0;
    }
    __syncthreads();
    const int is64 = s_is64;

    {
        bool a = false;
        if (tid < N) {
            long long lv;
            if (is64) lv = ((const long long*)label)[tid];
            else      lv = (long long)((const int*)label)[tid];
            a = (lv != 0);
        }
        unsigned b = __ballot_sync(0xffffffffu, a);
        if ((tid & 31) == 0 && (tid >> 5) < nwords)
            s_masks[tid >> 5] = b;
    }
    __syncthreads();

    int cnt = 0;
    #pragma unroll 4
    for (int j = 0; j < nwords; ++j) cnt += __popc(s_masks[j]);

    if (tid < N) {
        int w = tid >> 5, l = tid & 31;
        if ((s_masks[w] >> l) & 1u) {
            int pre = __popc(s_masks[w] & ((1u << l) - 1u));
            for (int j = 0; j < w; ++j) pre += __popc(s_masks[j]);
            s_rowOf[pre] = (short)tid;
        }
    }
    __syncthreads();

    // ---- gather-reduce over this block's chunk (if any) ----
    float acc = 0.0f;
    {
        const int q = blockIdx.x / chunksPerRow;     // active-row ordinal
        if (q < cnt) {
            const int chunk = blockIdx.x - q * chunksPerRow;
            const int row   = s_rowOf[q];
            const int p0    = chunk * CHUNK_PX + tid;
            const float* base = logits + (size_t)row * (size_t)K * (size_t)P;

            if (p0 + (PXPT - 1) * THREADS < P) {
                int c[PXPT];
                if (is64) {
                    const long long* s = (const long long*)seg + (size_t)row * P;
                    #pragma unroll
                    for (int i = 0; i < PXPT; ++i)
                        c[i] = (int)__ldg(s + p0 + THREADS * i);
                } else {
                    const int* s = (const int*)seg + (size_t)row * P;
                    #pragma unroll
                    for (int i = 0; i < PXPT; ++i)
                        c[i] = __ldg(s + p0 + THREADS * i);
                }
                float l[PXPT];
                #pragma unroll
                for (int i = 0; i < PXPT; ++i)
                    l[i] = __ldg(base + (size_t)c[i] * P + p0 + THREADS * i);
                #pragma unroll
                for (int i = 0; i < PXPT; ++i)
                    acc += focal_term(l[i]);
            } else {
                // tail chunk: scalar fallback over the chunk's valid pixels
                int pEnd = chunk * CHUNK_PX + CHUNK_PX;
                if (pEnd > P) pEnd = P;
                for (int p = p0; p < pEnd; p += THREADS) {
                    int cc;
                    if (is64) cc = (int)((const long long*)seg)[(size_t)row * P + p];
                    else      cc = ((const int*)seg)[(size_t)row * P + p];
                    acc += focal_term(__ldg(base + (size_t)cc * P + p));
                }
            }
        }
    }

    // ---- block reduction (8 warps) ----
    for (int off = 16; off > 0; off >>= 1)
        acc += __shfl_down_sync(0xffffffffu, acc, off);
    __shared__ double s_part[8];
    const int lane = tid & 31, wid = tid >> 5;
    if (lane == 0) s_part[wid] = (double)acc;
    __syncthreads();

    __shared__ int s_islast;
    if (tid == 0) {
        double v = 0.0;
        #pragma unroll
        for (int w = 0; w < 8; ++w) v += s_part[w];
        if (v != 0.0) atomicAdd(&g_total, v);
        __threadfence();
        unsigned old = atomicInc(&g_done, gridDim.x - 1u);
        s_islast = (old == gridDim.x - 1u) ? 1 : 0;
    }
    __syncthreads();

    // ---- last block: finalize ----
    if (s_islast) {
        __shared__ float s_loss;
        if (tid == 0) {
            double tot = *((volatile double*)&g_total);
            double cd  = (cnt > 0) ? (double)cnt : 1.0;
            s_loss = (float)(-tot / cd);
            g_total = 0.0;          // reset for next graph replay
            __threadfence();
        }
        __syncthreads();
        float loss = s_loss;
        for (int i = tid; i < out_size; i += blockDim.x)
            out[i] = (i == 0 || i == 2) ? loss : 0.0f;
    }
}

extern "C" void kernel_launch(void* const* d_in, const int* in_sizes, int n_in,
                              void* d_out, int out_size)
{
    const float* logits = (const float*)d_in[0];
    const void*  seg    = d_in[1];
    const void*  label  = d_in[2];

    int N = in_sizes[2];                 // B*S
    int P = in_sizes[1] / N;             // H*W
    int K = in_sizes[0] / in_sizes[1];   // classes

    int chunksPerRow = (P + CHUNK_PX - 1) / CHUNK_PX;
    unsigned int blocks = (unsigned int)N * (unsigned int)chunksPerRow;

    semiloss_fused<<<blocks, THREADS>>>(logits, seg, label,
                                        N, K, P, chunksPerRow,
                                        (float*)d_out, out_size);
}